// round 2
// baseline (speedup 1.0000x reference)
#include <cuda_runtime.h>
#include <math.h>

// Problem constants (static shapes from reference)
#define N_NODES 50000
#define N_EDGES 400000
#define TOT_E   (N_EDGES + N_NODES)   // 450000 incl. self-loops
#define IN_CH   128
#define OUT_CH  64
#define HEADS   8
#define F1      (HEADS * OUT_CH)      // 512

// ---------------- device scratch (static; no allocations allowed) ----------
__device__ __align__(16) float g_H1[N_NODES * F1];       // layer-1 features [N,8,64]
__device__ __align__(16) float g_num1[N_NODES * F1];     // layer-1 numerator accum
__device__ __align__(16) float g_as1[N_NODES * HEADS];
__device__ __align__(16) float g_ad1[N_NODES * HEADS];
__device__ __align__(16) float g_emax1[N_NODES * HEADS];
__device__ __align__(16) float g_den1[N_NODES * HEADS];
__device__ __align__(16) float g_X2[N_NODES * OUT_CH];   // ELU'd layer-1 output
__device__ __align__(16) float g_H2[N_NODES * OUT_CH];
__device__ __align__(16) float g_num2[N_NODES * OUT_CH];
__device__ __align__(16) float g_as2[N_NODES];
__device__ __align__(16) float g_ad2[N_NODES];
__device__ __align__(16) float g_emax2[N_NODES];
__device__ __align__(16) float g_den2[N_NODES];

__device__ __forceinline__ void atomicMaxFloat(float* addr, float val) {
    // standard sign-split trick: monotone toward max from either path
    if (val >= 0.f) atomicMax((int*)addr, __float_as_int(val));
    else            atomicMin((unsigned int*)addr, __float_as_uint(val));
}

__device__ __forceinline__ float lrelu(float v) { return v > 0.f ? v : 0.2f * v; }

// ---------------- init (graph replays: must reset every launch) ------------
__global__ void k_init() {
    int i = blockIdx.x * blockDim.x + threadIdx.x;
    if (i < N_NODES * F1)     g_num1[i] = 0.f;
    if (i < N_NODES * OUT_CH) g_num2[i] = 0.f;
    if (i < N_NODES * HEADS)  { g_den1[i] = 0.f; g_emax1[i] = __int_as_float(0xff800000); }
    if (i < N_NODES)          { g_den2[i] = 0.f; g_emax2[i] = __int_as_float(0xff800000); }
}

// ---------------- GEMM1: H1[N,512] = x[N,128] @ W1[128,512] ----------------
__global__ __launch_bounds__(256) void k_gemm1(const float* __restrict__ A,
                                               const float* __restrict__ B) {
    const int BM = 64, BN = 64, BK = 16;
    __shared__ float As[BK][BM + 4];   // padded vs bank conflicts
    __shared__ float Bs[BK][BN];
    int bn = blockIdx.x;               // 0..7
    int bm = blockIdx.y;               // 0..781
    int tid = threadIdx.x;
    int tx = tid & 15;                 // col group
    int ty = tid >> 4;                 // row group
    int m0 = bm * BM;
    float acc[4][4] = {};
    for (int k0 = 0; k0 < IN_CH; k0 += BK) {
        {   // A tile: 64 rows x 16 cols, float4/thread, coalesced
            int r  = tid >> 2;
            int kq = (tid & 3) * 4;
            int gm = m0 + r;
            float4 v = (gm < N_NODES) ? *(const float4*)(A + (size_t)gm * IN_CH + k0 + kq)
                                      : make_float4(0.f, 0.f, 0.f, 0.f);
            As[kq + 0][r] = v.x; As[kq + 1][r] = v.y;
            As[kq + 2][r] = v.z; As[kq + 3][r] = v.w;
        }
        {   // B tile: 16 rows x 64 cols
            int r  = tid >> 4;
            int cq = (tid & 15) * 4;
            float4 v = *(const float4*)(B + (size_t)(k0 + r) * F1 + bn * BN + cq);
            *(float4*)&Bs[r][cq] = v;
        }
        __syncthreads();
#pragma unroll
        for (int k = 0; k < BK; k++) {
            float4 a4 = *(const float4*)&As[k][ty * 4];
            float4 b4 = *(const float4*)&Bs[k][tx * 4];
            float a[4] = {a4.x, a4.y, a4.z, a4.w};
            float b[4] = {b4.x, b4.y, b4.z, b4.w};
#pragma unroll
            for (int i = 0; i < 4; i++)
#pragma unroll
                for (int j = 0; j < 4; j++) acc[i][j] += a[i] * b[j];
        }
        __syncthreads();
    }
#pragma unroll
    for (int i = 0; i < 4; i++) {
        int gm = m0 + ty * 4 + i;
        if (gm < N_NODES) {
            float4 v = make_float4(acc[i][0], acc[i][1], acc[i][2], acc[i][3]);
            *(float4*)(g_H1 + (size_t)gm * F1 + bn * BN + tx * 4) = v;
        }
    }
}

// ---------------- attention dots layer 1: warp per node --------------------
__global__ __launch_bounds__(256) void k_att1(const float* __restrict__ att_s,
                                              const float* __restrict__ att_d) {
    int warp = (blockIdx.x * blockDim.x + threadIdx.x) >> 5;
    int lane = threadIdx.x & 31;
    if (warp >= N_NODES) return;
    const float* hrow = g_H1 + (size_t)warp * F1;
#pragma unroll
    for (int h = 0; h < HEADS; h++) {
        float v1 = hrow[h * 64 + lane], v2 = hrow[h * 64 + 32 + lane];
        float s = v1 * att_s[h * 64 + lane] + v2 * att_s[h * 64 + 32 + lane];
        float d = v1 * att_d[h * 64 + lane] + v2 * att_d[h * 64 + 32 + lane];
#pragma unroll
        for (int o = 16; o; o >>= 1) {
            s += __shfl_xor_sync(0xffffffffu, s, o);
            d += __shfl_xor_sync(0xffffffffu, d, o);
        }
        if (lane == 0) { g_as1[warp * 8 + h] = s; g_ad1[warp * 8 + h] = d; }
    }
}

// ---------------- segment max layer 1: thread per (edge, head) -------------
__global__ void k_max1(const int* __restrict__ ei) {
    int i = blockIdx.x * blockDim.x + threadIdx.x;
    if (i >= TOT_E * HEADS) return;
    int e = i >> 3, h = i & 7;
    int s, d;
    if (e < N_EDGES) { s = ei[e]; d = ei[N_EDGES + e]; } else { s = d = e - N_EDGES; }
    float v = lrelu(g_as1[s * 8 + h] + g_ad1[d * 8 + h]);
    atomicMaxFloat(&g_emax1[d * 8 + h], v);
}

// ---- fused exp + denom + numerator accumulation, warp per edge ------------
__global__ __launch_bounds__(256) void k_agg1(const int* __restrict__ ei) {
    int warp = (blockIdx.x * blockDim.x + threadIdx.x) >> 5;
    int lane = threadIdx.x & 31;
    if (warp >= TOT_E) return;
    int s, d;
    if (warp < N_EDGES) { s = ei[warp]; d = ei[N_EDGES + warp]; } else { s = d = warp - N_EDGES; }
    float ee = 0.f;
    if (lane < HEADS) {
        float v = lrelu(g_as1[s * 8 + lane] + g_ad1[d * 8 + lane]);
        ee = __expf(v - g_emax1[d * 8 + lane]);
        atomicAdd(&g_den1[d * 8 + lane], ee);
    }
    const float* hrow = g_H1 + (size_t)s * F1;
    float* nrow = g_num1 + (size_t)d * F1;
#pragma unroll
    for (int i = 0; i < 4; i++) {
        int idx = i * 128 + lane * 4;
        int h = idx >> 6;                       // head for these 4 channels
        float w = __shfl_sync(0xffffffffu, ee, h);
        float4 v = *(const float4*)(hrow + idx);
        v.x *= w; v.y *= w; v.z *= w; v.w *= w;
        atomicAdd((float4*)(nrow + idx), v);    // sm_90+ vector RED
    }
}

// ---------------- finalize layer 1: mean heads + bias + ELU ----------------
__global__ void k_fin1(const float* __restrict__ b1) {
    int i = blockIdx.x * blockDim.x + threadIdx.x;
    if (i >= N_NODES * OUT_CH) return;
    int n = i >> 6, c = i & 63;
    float acc = 0.f;
#pragma unroll
    for (int h = 0; h < HEADS; h++)
        acc += g_num1[(size_t)n * F1 + h * 64 + c] / g_den1[n * 8 + h];
    float v = acc * 0.125f + b1[c];
    g_X2[i] = v > 0.f ? v : expm1f(v);
}

// ---------------- GEMM2: H2[N,64] = X2[N,64] @ W2[64,64] -------------------
__global__ __launch_bounds__(256) void k_gemm2(const float* __restrict__ W2) {
    __shared__ float ws[64 * 64];
    __shared__ float xs[16][64];
    int tid = threadIdx.x;
    for (int i = tid; i < 64 * 64; i += 256) ws[i] = W2[i];
    int r0 = blockIdx.x * 16;
    for (int i = tid; i < 16 * 64; i += 256) {
        int r = i >> 6, c = i & 63;
        xs[r][c] = g_X2[(size_t)(r0 + r) * 64 + c];
    }
    __syncthreads();
    int c  = tid & 63;
    int rg = tid >> 6;   // 0..3
    float acc[4] = {0.f, 0.f, 0.f, 0.f};
    for (int k = 0; k < 64; k++) {
        float w = ws[k * 64 + c];
#pragma unroll
        for (int j = 0; j < 4; j++) acc[j] += xs[rg * 4 + j][k] * w;
    }
#pragma unroll
    for (int j = 0; j < 4; j++)
        g_H2[(size_t)(r0 + rg * 4 + j) * 64 + c] = acc[j];
}

// ---------------- attention dots layer 2 -----------------------------------
__global__ __launch_bounds__(256) void k_att2(const float* __restrict__ att_s,
                                              const float* __restrict__ att_d) {
    int warp = (blockIdx.x * blockDim.x + threadIdx.x) >> 5;
    int lane = threadIdx.x & 31;
    if (warp >= N_NODES) return;
    const float* hrow = g_H2 + (size_t)warp * 64;
    float v1 = hrow[lane], v2 = hrow[32 + lane];
    float s = v1 * att_s[lane] + v2 * att_s[32 + lane];
    float d = v1 * att_d[lane] + v2 * att_d[32 + lane];
#pragma unroll
    for (int o = 16; o; o >>= 1) {
        s += __shfl_xor_sync(0xffffffffu, s, o);
        d += __shfl_xor_sync(0xffffffffu, d, o);
    }
    if (lane == 0) { g_as2[warp] = s; g_ad2[warp] = d; }
}

// ---------------- segment max layer 2: thread per edge ---------------------
__global__ void k_max2(const int* __restrict__ ei) {
    int e = blockIdx.x * blockDim.x + threadIdx.x;
    if (e >= TOT_E) return;
    int s, d;
    if (e < N_EDGES) { s = ei[e]; d = ei[N_EDGES + e]; } else { s = d = e - N_EDGES; }
    float v = lrelu(g_as2[s] + g_ad2[d]);
    atomicMaxFloat(&g_emax2[d], v);
}

// ---- fused layer-2 aggregation, warp per edge -----------------------------
__global__ __launch_bounds__(256) void k_agg2(const int* __restrict__ ei) {
    int warp = (blockIdx.x * blockDim.x + threadIdx.x) >> 5;
    int lane = threadIdx.x & 31;
    if (warp >= TOT_E) return;
    int s, d;
    if (warp < N_EDGES) { s = ei[warp]; d = ei[N_EDGES + warp]; } else { s = d = warp - N_EDGES; }
    float ee = 0.f;
    if (lane == 0) {
        float v = lrelu(g_as2[s] + g_ad2[d]);
        ee = __expf(v - g_emax2[d]);
        atomicAdd(&g_den2[d], ee);
    }
    ee = __shfl_sync(0xffffffffu, ee, 0);
    float2 v = *(const float2*)(g_H2 + (size_t)s * 64 + lane * 2);
    v.x *= ee; v.y *= ee;
    atomicAdd((float2*)(g_num2 + (size_t)d * 64 + lane * 2), v);
}

// ---------------- finalize layer 2 -----------------------------------------
__global__ void k_fin2(const float* __restrict__ b2, float* __restrict__ out) {
    int i = blockIdx.x * blockDim.x + threadIdx.x;
    if (i >= N_NODES * OUT_CH) return;
    out[i] = g_num2[i] / g_den2[i >> 6] + b2[i & 63];
}

// ---------------------------------------------------------------------------
extern "C" void kernel_launch(void* const* d_in, const int* in_sizes, int n_in,
                              void* d_out, int out_size) {
    const float* x   = (const float*)d_in[0];
    const int*   ei  = (const int*)  d_in[1];
    const float* W1  = (const float*)d_in[2];
    const float* as1 = (const float*)d_in[3];
    const float* ad1 = (const float*)d_in[4];
    const float* b1  = (const float*)d_in[5];
    const float* W2  = (const float*)d_in[6];
    const float* as2 = (const float*)d_in[7];
    const float* ad2 = (const float*)d_in[8];
    const float* b2  = (const float*)d_in[9];
    float* out = (float*)d_out;

    k_init<<<(N_NODES * F1 + 255) / 256, 256>>>();

    // layer 1
    k_gemm1<<<dim3(F1 / 64, (N_NODES + 63) / 64), 256>>>(x, W1);
    k_att1<<<(N_NODES + 7) / 8, 256>>>(as1, ad1);
    k_max1<<<(TOT_E * HEADS + 255) / 256, 256>>>(ei);
    k_agg1<<<(TOT_E + 7) / 8, 256>>>(ei);
    k_fin1<<<(N_NODES * OUT_CH + 255) / 256, 256>>>(b1);

    // layer 2
    k_gemm2<<<N_NODES / 16, 256>>>(W2);
    k_att2<<<(N_NODES + 7) / 8, 256>>>(as2, ad2);
    k_max2<<<(TOT_E + 255) / 256, 256>>>(ei);
    k_agg2<<<(TOT_E + 7) / 8, 256>>>(ei);
    k_fin2<<<(N_NODES * OUT_CH + 255) / 256, 256>>>(b2, out);
}

// round 3
// speedup vs baseline: 1.7354x; 1.7354x over previous
#include <cuda_runtime.h>
#include <math.h>

#define N_NODES 50000
#define N_EDGES 400000
#define TOT_E   (N_EDGES + N_NODES)
#define IN_CH   128
#define OUT_CH  64
#define HEADS   8
#define F1      (HEADS * OUT_CH)      // 512

// ---------------- device scratch -------------------------------------------
__device__ __align__(16) float g_H1[N_NODES * F1];
__device__ __align__(16) float g_as1[N_NODES * HEADS];
__device__ __align__(16) float g_ad1[N_NODES * HEADS];
__device__ __align__(16) float g_X2[N_NODES * OUT_CH];
__device__ __align__(16) float g_H2[N_NODES * OUT_CH];
__device__ __align__(16) float g_as2[N_NODES];
__device__ __align__(16) float g_ad2[N_NODES];
// CSR by destination
__device__ int g_deg[N_NODES];
__device__ int g_cursor[N_NODES];
__device__ int g_off[N_NODES + 1];
__device__ int g_csr_src[TOT_E];

__device__ __forceinline__ float lrelu(float v) { return v > 0.f ? v : 0.2f * v; }

// ---------------- init: only CSR counters now ------------------------------
__global__ void k_init() {
    int i = blockIdx.x * blockDim.x + threadIdx.x;
    if (i < N_NODES) { g_deg[i] = 0; g_cursor[i] = 0; }
}

// ---------------- CSR build -------------------------------------------------
__global__ void k_hist(const int* __restrict__ ei) {
    int e = blockIdx.x * blockDim.x + threadIdx.x;
    if (e >= TOT_E) return;
    int d = (e < N_EDGES) ? ei[N_EDGES + e] : e - N_EDGES;
    atomicAdd(&g_deg[d], 1);
}

__global__ __launch_bounds__(1024) void k_scan() {   // single block
    __shared__ int sp[1024];
    int t = threadIdx.x;
    const int CH = (N_NODES + 1023) / 1024;          // 49
    int base = t * CH;
    int s = 0;
    for (int i = 0; i < CH; i++) {
        int idx = base + i;
        if (idx < N_NODES) s += g_deg[idx];
    }
    sp[t] = s;
    __syncthreads();
    for (int o = 1; o < 1024; o <<= 1) {
        int v = (t >= o) ? sp[t - o] : 0;
        __syncthreads();
        sp[t] += v;
        __syncthreads();
    }
    int run = (t == 0) ? 0 : sp[t - 1];
    for (int i = 0; i < CH; i++) {
        int idx = base + i;
        if (idx < N_NODES) { g_off[idx] = run; run += g_deg[idx]; }
    }
    if (t == 1023) g_off[N_NODES] = sp[1023];
}

__global__ void k_scatter(const int* __restrict__ ei) {
    int e = blockIdx.x * blockDim.x + threadIdx.x;
    if (e >= TOT_E) return;
    int s, d;
    if (e < N_EDGES) { s = ei[e]; d = ei[N_EDGES + e]; } else { s = d = e - N_EDGES; }
    int pos = g_off[d] + atomicAdd(&g_cursor[d], 1);
    g_csr_src[pos] = s;
}

// ---------------- GEMM1 (128x64 tile, 8x4/thread) + fused att dots ---------
__global__ __launch_bounds__(256) void k_gemm1(const float* __restrict__ A,
                                               const float* __restrict__ B,
                                               const float* __restrict__ att_s,
                                               const float* __restrict__ att_d) {
    const int BM = 128, BK = 16;
    __shared__ float As[BK][BM + 4];
    __shared__ float Bs[BK][64];
    int bn = blockIdx.x;               // head / 64-col group: 0..7
    int bm = blockIdx.y;
    int tid = threadIdx.x;
    int tx = tid & 15;                 // 4 cols each
    int ty = tid >> 4;                 // 8 rows each
    int m0 = bm * BM;
    float acc[8][4] = {};
    for (int k0 = 0; k0 < IN_CH; k0 += BK) {
#pragma unroll
        for (int q = 0; q < 2; q++) {  // A tile: 128x16 = 512 float4
            int f = tid + q * 256;
            int r = f >> 2, kq = (f & 3) * 4;
            int gm = m0 + r;
            float4 v = (gm < N_NODES) ? *(const float4*)(A + (size_t)gm * IN_CH + k0 + kq)
                                      : make_float4(0.f, 0.f, 0.f, 0.f);
            As[kq + 0][r] = v.x; As[kq + 1][r] = v.y;
            As[kq + 2][r] = v.z; As[kq + 3][r] = v.w;
        }
        {   // B tile: 16x64
            int r = tid >> 4, cq = (tid & 15) * 4;
            *(float4*)&Bs[r][cq] = *(const float4*)(B + (size_t)(k0 + r) * F1 + bn * 64 + cq);
        }
        __syncthreads();
#pragma unroll
        for (int k = 0; k < BK; k++) {
            float a[8], b[4];
            *(float4*)(a)     = *(const float4*)&As[k][ty * 8];
            *(float4*)(a + 4) = *(const float4*)&As[k][ty * 8 + 4];
            *(float4*)(b)     = *(const float4*)&Bs[k][tx * 4];
#pragma unroll
            for (int i = 0; i < 8; i++)
#pragma unroll
                for (int j = 0; j < 4; j++) acc[i][j] += a[i] * b[j];
        }
        __syncthreads();
    }
    // epilogue: store H1 + attention dots for this head (bn)
    float sa[4], da[4];
    *(float4*)sa = *(const float4*)(att_s + bn * 64 + tx * 4);
    *(float4*)da = *(const float4*)(att_d + bn * 64 + tx * 4);
#pragma unroll
    for (int i = 0; i < 8; i++) {
        int gm = m0 + ty * 8 + i;
        bool ok = gm < N_NODES;
        float4 v = make_float4(acc[i][0], acc[i][1], acc[i][2], acc[i][3]);
        if (ok) *(float4*)(g_H1 + (size_t)gm * F1 + bn * 64 + tx * 4) = v;
        float ps = v.x * sa[0] + v.y * sa[1] + v.z * sa[2] + v.w * sa[3];
        float pd = v.x * da[0] + v.y * da[1] + v.z * da[2] + v.w * da[3];
#pragma unroll
        for (int o = 8; o; o >>= 1) {   // reduce over 16-lane row group
            ps += __shfl_xor_sync(0xffffffffu, ps, o);
            pd += __shfl_xor_sync(0xffffffffu, pd, o);
        }
        if (ok && tx == 0) { g_as1[gm * 8 + bn] = ps; g_ad1[gm * 8 + bn] = pd; }
    }
}

// ---- layer-1 CSR aggregation, warp per dst, fused softmax+mean+bias+ELU ---
__global__ __launch_bounds__(256) void k_agg1(const float* __restrict__ b1) {
    int d = (blockIdx.x * blockDim.x + threadIdx.x) >> 5;
    int lane = threadIdx.x & 31;
    if (d >= N_NODES) return;
    int beg = g_off[d], end = g_off[d + 1];
    float ad = (lane < HEADS) ? g_ad1[d * 8 + lane] : 0.f;
    float den = 0.f;
    float4 acc[4] = {};
    int hsel = (lane >> 4);            // which of the two heads per i-group
    for (int k = beg; k < end; k++) {
        int s = g_csr_src[k];
        float ee = 0.f;
        if (lane < HEADS) {
            float e = lrelu(g_as1[s * 8 + lane] + ad);
            ee = __expf(e);
            den += ee;
        }
        const float4* hp = (const float4*)(g_H1 + (size_t)s * F1);
#pragma unroll
        for (int i = 0; i < 4; i++) {
            // float idx = i*128 + lane*4 ; head = i*2 + (lane>>4)
            float w = __shfl_sync(0xffffffffu, ee, i * 2 + hsel);
            float4 v = hp[i * 32 + lane];
            acc[i].x += w * v.x; acc[i].y += w * v.y;
            acc[i].z += w * v.z; acc[i].w += w * v.w;
        }
    }
    // combine heads: div by per-head denom, sum over heads, /8, +bias, ELU
    float4 t = make_float4(0.f, 0.f, 0.f, 0.f);
#pragma unroll
    for (int i = 0; i < 4; i++) {
        float dh = __shfl_sync(0xffffffffu, den, i * 2 + hsel);
        float inv = 1.f / dh;
        t.x += acc[i].x * inv; t.y += acc[i].y * inv;
        t.z += acc[i].z * inv; t.w += acc[i].w * inv;
    }
    t.x += __shfl_xor_sync(0xffffffffu, t.x, 16);
    t.y += __shfl_xor_sync(0xffffffffu, t.y, 16);
    t.z += __shfl_xor_sync(0xffffffffu, t.z, 16);
    t.w += __shfl_xor_sync(0xffffffffu, t.w, 16);
    if (lane < 16) {
        int cc = lane * 4;
        float4 bb = *(const float4*)(b1 + cc);
        float4 o;
        o.x = t.x * 0.125f + bb.x; o.y = t.y * 0.125f + bb.y;
        o.z = t.z * 0.125f + bb.z; o.w = t.w * 0.125f + bb.w;
        o.x = o.x > 0.f ? o.x : expm1f(o.x);
        o.y = o.y > 0.f ? o.y : expm1f(o.y);
        o.z = o.z > 0.f ? o.z : expm1f(o.z);
        o.w = o.w > 0.f ? o.w : expm1f(o.w);
        *(float4*)(g_X2 + (size_t)d * OUT_CH + cc) = o;
    }
}

// ---------------- GEMM2: H2[N,64] = X2[N,64] @ W2[64,64] -------------------
__global__ __launch_bounds__(256) void k_gemm2(const float* __restrict__ W2) {
    __shared__ float ws[64 * 64];
    __shared__ float xs[16][64];
    int tid = threadIdx.x;
    for (int i = tid; i < 64 * 64; i += 256) ws[i] = W2[i];
    int r0 = blockIdx.x * 16;
    for (int i = tid; i < 16 * 64; i += 256) {
        int r = i >> 6, c = i & 63;
        xs[r][c] = g_X2[(size_t)(r0 + r) * 64 + c];
    }
    __syncthreads();
    int c = tid & 63;
    int rg = tid >> 6;
    float acc[4] = {0.f, 0.f, 0.f, 0.f};
    for (int k = 0; k < 64; k++) {
        float w = ws[k * 64 + c];
#pragma unroll
        for (int j = 0; j < 4; j++) acc[j] += xs[rg * 4 + j][k] * w;
    }
#pragma unroll
    for (int j = 0; j < 4; j++)
        g_H2[(size_t)(r0 + rg * 4 + j) * 64 + c] = acc[j];
}

// ---------------- attention dots layer 2 -----------------------------------
__global__ __launch_bounds__(256) void k_att2(const float* __restrict__ att_s,
                                              const float* __restrict__ att_d) {
    int warp = (blockIdx.x * blockDim.x + threadIdx.x) >> 5;
    int lane = threadIdx.x & 31;
    if (warp >= N_NODES) return;
    const float* hrow = g_H2 + (size_t)warp * 64;
    float v1 = hrow[lane], v2 = hrow[32 + lane];
    float s = v1 * att_s[lane] + v2 * att_s[32 + lane];
    float d = v1 * att_d[lane] + v2 * att_d[32 + lane];
#pragma unroll
    for (int o = 16; o; o >>= 1) {
        s += __shfl_xor_sync(0xffffffffu, s, o);
        d += __shfl_xor_sync(0xffffffffu, d, o);
    }
    if (lane == 0) { g_as2[warp] = s; g_ad2[warp] = d; }
}

// ---- layer-2 CSR aggregation, warp per dst, writes final output -----------
__global__ __launch_bounds__(256) void k_agg2(const float* __restrict__ b2,
                                              float* __restrict__ out) {
    int d = (blockIdx.x * blockDim.x + threadIdx.x) >> 5;
    int lane = threadIdx.x & 31;
    if (d >= N_NODES) return;
    int beg = g_off[d], end = g_off[d + 1];
    float ad = g_ad2[d];
    float den = 0.f;
    float2 acc = make_float2(0.f, 0.f);
    for (int k = beg; k < end; k++) {
        int s = g_csr_src[k];
        float ee = __expf(lrelu(g_as2[s] + ad));   // same value on all lanes
        den += ee;
        float2 v = *(const float2*)(g_H2 + (size_t)s * 64 + lane * 2);
        acc.x += ee * v.x; acc.y += ee * v.y;
    }
    float inv = 1.f / den;
    float2 bb = *(const float2*)(b2 + lane * 2);
    float2 o = make_float2(acc.x * inv + bb.x, acc.y * inv + bb.y);
    *(float2*)(out + (size_t)d * 64 + lane * 2) = o;
}

// ---------------------------------------------------------------------------
extern "C" void kernel_launch(void* const* d_in, const int* in_sizes, int n_in,
                              void* d_out, int out_size) {
    const float* x   = (const float*)d_in[0];
    const int*   ei  = (const int*)  d_in[1];
    const float* W1  = (const float*)d_in[2];
    const float* as1 = (const float*)d_in[3];
    const float* ad1 = (const float*)d_in[4];
    const float* b1  = (const float*)d_in[5];
    const float* W2  = (const float*)d_in[6];
    const float* as2 = (const float*)d_in[7];
    const float* ad2 = (const float*)d_in[8];
    const float* b2  = (const float*)d_in[9];
    float* out = (float*)d_out;

    k_init<<<(N_NODES + 255) / 256, 256>>>();
    k_hist<<<(TOT_E + 255) / 256, 256>>>(ei);
    k_scan<<<1, 1024>>>();
    k_scatter<<<(TOT_E + 255) / 256, 256>>>(ei);

    // layer 1
    k_gemm1<<<dim3(F1 / 64, (N_NODES + 127) / 128), 256>>>(x, W1, as1, ad1);
    k_agg1<<<(N_NODES * 32 + 255) / 256, 256>>>(b1);

    // layer 2
    k_gemm2<<<N_NODES / 16, 256>>>(W2);
    k_att2<<<(N_NODES + 7) / 8, 256>>>(as2, ad2);
    k_agg2<<<(N_NODES * 32 + 255) / 256, 256>>>(b2, out);
}

// round 5
// speedup vs baseline: 1.9611x; 1.1301x over previous
#include <cuda_runtime.h>
#include <cuda_bf16.h>
#include <math.h>
#include <stdint.h>

#define N_NODES 50000
#define N_EDGES 400000
#define TOT_E   (N_EDGES + N_NODES)
#define IN_CH   128
#define OUT_CH  64
#define HEADS   8
#define F1      (HEADS * OUT_CH)      // 512
#define M_TILES 391
#define M_PAD   (M_TILES * 128)       // 50048

// ---------------- device scratch -------------------------------------------
__device__ __align__(16) float g_H1[N_NODES * F1];
__device__ __align__(16) float g_as1[N_NODES * HEADS];
__device__ __align__(16) float g_ad1[N_NODES * HEADS];
__device__ __align__(16) float g_X2[N_NODES * OUT_CH];
__device__ __align__(16) float g_H2[N_NODES * OUT_CH];
__device__ __align__(16) float g_as2[N_NODES];
__device__ __align__(16) float g_ad2[N_NODES];
__device__ __align__(16) __nv_bfloat16 g_xhi[M_PAD * IN_CH];
__device__ __align__(16) __nv_bfloat16 g_xlo[M_PAD * IN_CH];
__device__ __align__(16) __nv_bfloat16 g_w1hi[F1 * IN_CH];   // [n][k] transposed
__device__ __align__(16) __nv_bfloat16 g_w1lo[F1 * IN_CH];
// CSR by destination
__device__ int g_deg[N_NODES];
__device__ int g_cursor[N_NODES];
__device__ int g_off[N_NODES + 1];
__device__ int g_csr_src[TOT_E];

__device__ __forceinline__ float lrelu(float v) { return v > 0.f ? v : 0.2f * v; }

__device__ __forceinline__ uint32_t smem_u32(const void* p) {
    uint32_t a;
    asm("{ .reg .u64 t; cvta.to.shared.u64 t, %1; cvt.u32.u64 %0, t; }"
        : "=r"(a) : "l"(p));
    return a;
}
__device__ __forceinline__ void ldsm4(uint32_t* r, uint32_t addr) {
    asm volatile("ldmatrix.sync.aligned.m8n8.x4.shared.b16 {%0,%1,%2,%3}, [%4];"
                 : "=r"(r[0]), "=r"(r[1]), "=r"(r[2]), "=r"(r[3]) : "r"(addr));
}
__device__ __forceinline__ void mma16816(float* d, const uint32_t* a,
                                         const uint32_t b0, const uint32_t b1) {
    asm volatile("mma.sync.aligned.m16n8k16.row.col.f32.bf16.bf16.f32 "
                 "{%0,%1,%2,%3}, {%4,%5,%6,%7}, {%8,%9}, {%0,%1,%2,%3};"
                 : "+f"(d[0]), "+f"(d[1]), "+f"(d[2]), "+f"(d[3])
                 : "r"(a[0]), "r"(a[1]), "r"(a[2]), "r"(a[3]), "r"(b0), "r"(b1));
}

// ---------------- init + CSR build -----------------------------------------
__global__ void k_init() {
    int i = blockIdx.x * blockDim.x + threadIdx.x;
    if (i < N_NODES) { g_deg[i] = 0; g_cursor[i] = 0; }
}
__global__ void k_hist(const int* __restrict__ ei) {
    int e = blockIdx.x * blockDim.x + threadIdx.x;
    if (e >= TOT_E) return;
    int d = (e < N_EDGES) ? ei[N_EDGES + e] : e - N_EDGES;
    atomicAdd(&g_deg[d], 1);
}
__global__ __launch_bounds__(1024) void k_scan() {
    __shared__ int sp[1024];
    int t = threadIdx.x;
    const int CH = (N_NODES + 1023) / 1024;
    int base = t * CH, s = 0;
    for (int i = 0; i < CH; i++) { int idx = base + i; if (idx < N_NODES) s += g_deg[idx]; }
    sp[t] = s;
    __syncthreads();
    for (int o = 1; o < 1024; o <<= 1) {
        int v = (t >= o) ? sp[t - o] : 0;
        __syncthreads();
        sp[t] += v;
        __syncthreads();
    }
    int run = (t == 0) ? 0 : sp[t - 1];
    for (int i = 0; i < CH; i++) {
        int idx = base + i;
        if (idx < N_NODES) { g_off[idx] = run; run += g_deg[idx]; }
    }
    if (t == 1023) g_off[N_NODES] = sp[1023];
}
__global__ void k_scatter(const int* __restrict__ ei) {
    int e = blockIdx.x * blockDim.x + threadIdx.x;
    if (e >= TOT_E) return;
    int s, d;
    if (e < N_EDGES) { s = ei[e]; d = ei[N_EDGES + e]; } else { s = d = e - N_EDGES; }
    int pos = g_off[d] + atomicAdd(&g_cursor[d], 1);
    g_csr_src[pos] = s;
}

// ---------------- bf16 hi/lo conversions -----------------------------------
__global__ void k_cvt_x(const float* __restrict__ x) {
    int i = blockIdx.x * blockDim.x + threadIdx.x;
    if (i >= M_PAD * IN_CH) return;
    float v = (i < N_NODES * IN_CH) ? x[i] : 0.f;
    __nv_bfloat16 hi = __float2bfloat16_rn(v);
    g_xhi[i] = hi;
    g_xlo[i] = __float2bfloat16_rn(v - __bfloat162float(hi));
}
__global__ void k_cvt_w(const float* __restrict__ W1) {
    int i = blockIdx.x * blockDim.x + threadIdx.x;
    if (i >= F1 * IN_CH) return;
    int n = i >> 7, k = i & 127;
    float v = W1[(size_t)k * F1 + n];
    __nv_bfloat16 hi = __float2bfloat16_rn(v);
    g_w1hi[i] = hi;
    g_w1lo[i] = __float2bfloat16_rn(v - __bfloat162float(hi));
}

// ======== GEMM1 via mma.sync bf16 hi/lo: H1 = x @ W1, fused att dots =======
// SMEM tile row stride: 136 bf16 = 272 bytes (conflict-free ldmatrix)
#define LDT 136
#define TILE_BYTES (128 * LDT * 2)    // 34816
// shared layout (bytes)
#define SH_ATTS 0
#define SH_ATTD 2048
#define SH_A_HI 4096
#define SH_A_LO (SH_A_HI + TILE_BYTES)
#define SH_B_HI (SH_A_LO + TILE_BYTES)
#define SH_B_LO (SH_B_HI + TILE_BYTES)
#define SH_TOTAL (SH_B_LO + TILE_BYTES)

__device__ __forceinline__ void load_tile128(char* dst, const __nv_bfloat16* src, int tid) {
#pragma unroll
    for (int it = 0; it < 16; it++) {
        int f = it * 256 + tid;          // 8-byte chunk id, 0..4095
        int r = f >> 5;
        int c8 = (f & 31);               // which uint2 in the row
        *(uint2*)(dst + r * (LDT * 2) + c8 * 8) =
            *(const uint2*)(src + (size_t)r * 128 + c8 * 4);
    }
}

__global__ __launch_bounds__(256) void k_mma1(const float* __restrict__ att_s,
                                              const float* __restrict__ att_d) {
    extern __shared__ char smem[];
    int tid = threadIdx.x;
    int wid = tid >> 5, lane = tid & 31;
    int wm = wid & 3;        // m group (32 rows)
    int wn = wid >> 2;       // n half (64 cols of the 128-chunk)
    int m0 = blockIdx.x * 128;

    // stage att vectors
    for (int i = tid; i < 512; i += 256) {
        ((float*)(smem + SH_ATTS))[i] = att_s[i];
        ((float*)(smem + SH_ATTD))[i] = att_d[i];
    }
    // A tiles
    load_tile128(smem + SH_A_HI, g_xhi + (size_t)m0 * 128, tid);
    load_tile128(smem + SH_A_LO, g_xlo + (size_t)m0 * 128, tid);

    uint32_t sb = smem_u32(smem);
    uint32_t abase[3] = { sb + SH_A_HI, sb + SH_A_HI, sb + SH_A_LO };
    uint32_t bbase[3] = { sb + SH_B_HI, sb + SH_B_LO, sb + SH_B_HI };

    // per-lane invariant row offsets for ldmatrix
    uint32_t a_row_off[2], b_row_off[4];
#pragma unroll
    for (int mf = 0; mf < 2; mf++)
        a_row_off[mf] = (uint32_t)(wm * 32 + mf * 16 + (lane & 7) + ((lane >> 3) & 1) * 8) * (LDT * 2);
#pragma unroll
    for (int jj = 0; jj < 4; jj++)
        b_row_off[jj] = (uint32_t)(wn * 64 + jj * 16 + (lane & 7) + (lane >> 4) * 8) * (LDT * 2);
    uint32_t a_k_lane = ((uint32_t)(lane >> 4) * 8) * 2;
    uint32_t b_k_lane = ((uint32_t)((lane >> 3) & 1) * 8) * 2;

    const float* sas = (const float*)(smem + SH_ATTS);
    const float* sad = (const float*)(smem + SH_ATTD);

    for (int chunk = 0; chunk < 4; chunk++) {
        __syncthreads();     // previous chunk's B reads done
        load_tile128(smem + SH_B_HI, g_w1hi + (size_t)chunk * 128 * 128, tid);
        load_tile128(smem + SH_B_LO, g_w1lo + (size_t)chunk * 128 * 128, tid);
        __syncthreads();

        float acc[2][8][4];
#pragma unroll
        for (int mf = 0; mf < 2; mf++)
#pragma unroll
            for (int nf = 0; nf < 8; nf++)
#pragma unroll
                for (int q = 0; q < 4; q++) acc[mf][nf][q] = 0.f;

        for (int term = 0; term < 3; term++) {
            uint32_t ab = abase[term], bb = bbase[term];
            for (int kb = 0; kb < 8; kb++) {
                uint32_t akoff = (uint32_t)(kb * 16) * 2 + a_k_lane;
                uint32_t bkoff = (uint32_t)(kb * 16) * 2 + b_k_lane;
                uint32_t afr[2][4], bfr[4][4];
#pragma unroll
                for (int mf = 0; mf < 2; mf++) ldsm4(afr[mf], ab + a_row_off[mf] + akoff);
#pragma unroll
                for (int jj = 0; jj < 4; jj++) ldsm4(bfr[jj], bb + b_row_off[jj] + bkoff);
#pragma unroll
                for (int mf = 0; mf < 2; mf++)
#pragma unroll
                    for (int nf = 0; nf < 8; nf++)
                        mma16816(acc[mf][nf], afr[mf],
                                 bfr[nf >> 1][(nf & 1) * 2], bfr[nf >> 1][(nf & 1) * 2 + 1]);
            }
        }

        // epilogue for this chunk: head = chunk*2 + wn covers exactly these 64 cols
        int head = chunk * 2 + wn;
        float ps[2][2] = {}, pd[2][2] = {};
#pragma unroll
        for (int nf = 0; nf < 8; nf++) {
            int cl = nf * 8 + (lane & 3) * 2;         // col within head
            int col = head * 64 + cl;
            float2 wa = *(const float2*)(sas + col);
            float2 wd = *(const float2*)(sad + col);
#pragma unroll
            for (int mf = 0; mf < 2; mf++)
#pragma unroll
                for (int rh = 0; rh < 2; rh++) {
                    float d0 = acc[mf][nf][rh * 2], d1 = acc[mf][nf][rh * 2 + 1];
                    int row = m0 + wm * 32 + mf * 16 + rh * 8 + (lane >> 2);
                    if (row < N_NODES)
                        *(float2*)(g_H1 + (size_t)row * F1 + col) = make_float2(d0, d1);
                    ps[mf][rh] += d0 * wa.x + d1 * wa.y;
                    pd[mf][rh] += d0 * wd.x + d1 * wd.y;
                }
        }
#pragma unroll
        for (int mf = 0; mf < 2; mf++)
#pragma unroll
            for (int rh = 0; rh < 2; rh++) {
                float s = ps[mf][rh], d = pd[mf][rh];
                s += __shfl_xor_sync(0xffffffffu, s, 1);
                s += __shfl_xor_sync(0xffffffffu, s, 2);
                d += __shfl_xor_sync(0xffffffffu, d, 1);
                d += __shfl_xor_sync(0xffffffffu, d, 2);
                int row = m0 + wm * 32 + mf * 16 + rh * 8 + (lane >> 2);
                if ((lane & 3) == 0 && row < N_NODES) {
                    g_as1[row * 8 + head] = s;
                    g_ad1[row * 8 + head] = d;
                }
            }
    }
}

// ---- layer-1 CSR aggregation, warp per dst, fused softmax+mean+bias+ELU ---
__global__ __launch_bounds__(256) void k_agg1(const float* __restrict__ b1) {
    int d = (blockIdx.x * blockDim.x + threadIdx.x) >> 5;
    int lane = threadIdx.x & 31;
    if (d >= N_NODES) return;
    int beg = g_off[d], end = g_off[d + 1];
    float ad = (lane < HEADS) ? g_ad1[d * 8 + lane] : 0.f;
    float den = 0.f;
    float4 acc[4] = {};
    int hsel = (lane >> 4);
    for (int k = beg; k < end; k++) {
        int s = g_csr_src[k];
        float ee = 0.f;
        if (lane < HEADS) {
            float e = lrelu(g_as1[s * 8 + lane] + ad);
            ee = __expf(e);
            den += ee;
        }
        const float4* hp = (const float4*)(g_H1 + (size_t)s * F1);
#pragma unroll
        for (int i = 0; i < 4; i++) {
            float w = __shfl_sync(0xffffffffu, ee, i * 2 + hsel);
            float4 v = hp[i * 32 + lane];
            acc[i].x += w * v.x; acc[i].y += w * v.y;
            acc[i].z += w * v.z; acc[i].w += w * v.w;
        }
    }
    float4 t = make_float4(0.f, 0.f, 0.f, 0.f);
#pragma unroll
    for (int i = 0; i < 4; i++) {
        float dh = __shfl_sync(0xffffffffu, den, i * 2 + hsel);
        float inv = 1.f / dh;
        t.x += acc[i].x * inv; t.y += acc[i].y * inv;
        t.z += acc[i].z * inv; t.w += acc[i].w * inv;
    }
    t.x += __shfl_xor_sync(0xffffffffu, t.x, 16);
    t.y += __shfl_xor_sync(0xffffffffu, t.y, 16);
    t.z += __shfl_xor_sync(0xffffffffu, t.z, 16);
    t.w += __shfl_xor_sync(0xffffffffu, t.w, 16);
    if (lane < 16) {
        int cc = lane * 4;
        float4 bb = *(const float4*)(b1 + cc);
        float4 o;
        o.x = t.x * 0.125f + bb.x; o.y = t.y * 0.125f + bb.y;
        o.z = t.z * 0.125f + bb.z; o.w = t.w * 0.125f + bb.w;
        o.x = o.x > 0.f ? o.x : expm1f(o.x);
        o.y = o.y > 0.f ? o.y : expm1f(o.y);
        o.z = o.z > 0.f ? o.z : expm1f(o.z);
        o.w = o.w > 0.f ? o.w : expm1f(o.w);
        *(float4*)(g_X2 + (size_t)d * OUT_CH + cc) = o;
    }
}

// ---------------- GEMM2: H2[N,64] = X2[N,64] @ W2[64,64] -------------------
__global__ __launch_bounds__(256) void k_gemm2(const float* __restrict__ W2) {
    __shared__ float ws[64 * 64];
    __shared__ float xs[16][64];
    int tid = threadIdx.x;
    for (int i = tid; i < 64 * 64; i += 256) ws[i] = W2[i];
    int r0 = blockIdx.x * 16;
    for (int i = tid; i < 16 * 64; i += 256) {
        int r = i >> 6, c = i & 63;
        xs[r][c] = g_X2[(size_t)(r0 + r) * 64 + c];
    }
    __syncthreads();
    int c = tid & 63;
    int rg = tid >> 6;
    float acc[4] = {0.f, 0.f, 0.f, 0.f};
    for (int k = 0; k < 64; k++) {
        float w = ws[k * 64 + c];
#pragma unroll
        for (int j = 0; j < 4; j++) acc[j] += xs[rg * 4 + j][k] * w;
    }
#pragma unroll
    for (int j = 0; j < 4; j++)
        g_H2[(size_t)(r0 + rg * 4 + j) * 64 + c] = acc[j];
}

// ---------------- attention dots layer 2 -----------------------------------
__global__ __launch_bounds__(256) void k_att2(const float* __restrict__ att_s,
                                              const float* __restrict__ att_d) {
    int warp = (blockIdx.x * blockDim.x + threadIdx.x) >> 5;
    int lane = threadIdx.x & 31;
    if (warp >= N_NODES) return;
    const float* hrow = g_H2 + (size_t)warp * 64;
    float v1 = hrow[lane], v2 = hrow[32 + lane];
    float s = v1 * att_s[lane] + v2 * att_s[32 + lane];
    float d = v1 * att_d[lane] + v2 * att_d[32 + lane];
#pragma unroll
    for (int o = 16; o; o >>= 1) {
        s += __shfl_xor_sync(0xffffffffu, s, o);
        d += __shfl_xor_sync(0xffffffffu, d, o);
    }
    if (lane == 0) { g_as2[warp] = s; g_ad2[warp] = d; }
}

// ---- layer-2 CSR aggregation, warp per dst, writes final output -----------
__global__ __launch_bounds__(256) void k_agg2(const float* __restrict__ b2,
                                              float* __restrict__ out) {
    int d = (blockIdx.x * blockDim.x + threadIdx.x) >> 5;
    int lane = threadIdx.x & 31;
    if (d >= N_NODES) return;
    int beg = g_off[d], end = g_off[d + 1];
    float ad = g_ad2[d];
    float den = 0.f;
    float2 acc = make_float2(0.f, 0.f);
    for (int k = beg; k < end; k++) {
        int s = g_csr_src[k];
        float ee = __expf(lrelu(g_as2[s] + ad));
        den += ee;
        float2 v = *(const float2*)(g_H2 + (size_t)s * 64 + lane * 2);
        acc.x += ee * v.x; acc.y += ee * v.y;
    }
    float inv = 1.f / den;
    float2 bb = *(const float2*)(b2 + lane * 2);
    *(float2*)(out + (size_t)d * 64 + lane * 2) =
        make_float2(acc.x * inv + bb.x, acc.y * inv + bb.y);
}

// ---------------------------------------------------------------------------
extern "C" void kernel_launch(void* const* d_in, const int* in_sizes, int n_in,
                              void* d_out, int out_size) {
    const float* x   = (const float*)d_in[0];
    const int*   ei  = (const int*)  d_in[1];
    const float* W1  = (const float*)d_in[2];
    const float* as1 = (const float*)d_in[3];
    const float* ad1 = (const float*)d_in[4];
    const float* b1  = (const float*)d_in[5];
    const float* W2  = (const float*)d_in[6];
    const float* as2 = (const float*)d_in[7];
    const float* ad2 = (const float*)d_in[8];
    const float* b2  = (const float*)d_in[9];
    float* out = (float*)d_out;

    static int smem_set = 0;
    if (!smem_set) {
        cudaFuncSetAttribute(k_mma1, cudaFuncAttributeMaxDynamicSharedMemorySize, SH_TOTAL);
        smem_set = 1;
    }

    k_init<<<(N_NODES + 255) / 256, 256>>>();
    k_hist<<<(TOT_E + 255) / 256, 256>>>(ei);
    k_scan<<<1, 1024>>>();
    k_scatter<<<(TOT_E + 255) / 256, 256>>>(ei);

    k_cvt_x<<<(M_PAD * IN_CH + 255) / 256, 256>>>(x);
    k_cvt_w<<<(F1 * IN_CH + 255) / 256, 256>>>(W1);

    // layer 1
    k_mma1<<<M_TILES, 256, SH_TOTAL>>>(as1, ad1);
    k_agg1<<<(N_NODES * 32 + 255) / 256, 256>>>(b1);

    // layer 2
    k_gemm2<<<N_NODES / 16, 256>>>(W2);
    k_att2<<<(N_NODES + 7) / 8, 256>>>(as2, ad2);
    k_agg2<<<(N_NODES * 32 + 255) / 256, 256>>>(b2, out);
}

// round 6
// speedup vs baseline: 2.5178x; 1.2839x over previous
#include <cuda_runtime.h>
#include <cuda_bf16.h>
#include <cuda_fp16.h>
#include <math.h>
#include <stdint.h>

#define N_NODES 50000
#define N_EDGES 400000
#define TOT_E   (N_EDGES + N_NODES)
#define IN_CH   128
#define OUT_CH  64
#define HEADS   8
#define F1      (HEADS * OUT_CH)      // 512
#define M_TILES 391

// ---------------- device scratch -------------------------------------------
__device__ __align__(16) __half g_H1h[N_NODES * F1];     // layer-1 features, fp16
__device__ __align__(16) float g_as1[N_NODES * HEADS];
__device__ __align__(16) float g_ad1[N_NODES * HEADS];
__device__ __align__(16) float g_X2[N_NODES * OUT_CH];
__device__ __align__(16) __half g_H2h[N_NODES * OUT_CH];
__device__ __align__(16) float g_as2[N_NODES];
__device__ __align__(16) float g_ad2[N_NODES];
__device__ __align__(16) __nv_bfloat16 g_w1hi[F1 * IN_CH];   // [n][k] transposed
__device__ __align__(16) __nv_bfloat16 g_w1lo[F1 * IN_CH];
// CSR by destination
__device__ int g_deg[N_NODES];
__device__ int g_cursor[N_NODES];
__device__ int g_off[N_NODES + 1];
__device__ int g_csr_src[TOT_E];

__device__ __forceinline__ float lrelu(float v) { return v > 0.f ? v : 0.2f * v; }

__device__ __forceinline__ uint32_t smem_u32(const void* p) {
    uint32_t a;
    asm("{ .reg .u64 t; cvta.to.shared.u64 t, %1; cvt.u32.u64 %0, t; }"
        : "=r"(a) : "l"(p));
    return a;
}
__device__ __forceinline__ void ldsm4(uint32_t* r, uint32_t addr) {
    asm volatile("ldmatrix.sync.aligned.m8n8.x4.shared.b16 {%0,%1,%2,%3}, [%4];"
                 : "=r"(r[0]), "=r"(r[1]), "=r"(r[2]), "=r"(r[3]) : "r"(addr));
}
__device__ __forceinline__ void mma16816(float* d, const uint32_t* a,
                                         const uint32_t b0, const uint32_t b1) {
    asm volatile("mma.sync.aligned.m16n8k16.row.col.f32.bf16.bf16.f32 "
                 "{%0,%1,%2,%3}, {%4,%5,%6,%7}, {%8,%9}, {%0,%1,%2,%3};"
                 : "+f"(d[0]), "+f"(d[1]), "+f"(d[2]), "+f"(d[3])
                 : "r"(a[0]), "r"(a[1]), "r"(a[2]), "r"(a[3]), "r"(b0), "r"(b1));
}

// ---------------- init + CSR build -----------------------------------------
__global__ void k_init() {
    int i = blockIdx.x * blockDim.x + threadIdx.x;
    if (i < N_NODES) { g_deg[i] = 0; g_cursor[i] = 0; }
}
__global__ void k_hist(const int* __restrict__ ei) {
    int e = blockIdx.x * blockDim.x + threadIdx.x;
    if (e >= TOT_E) return;
    int d = (e < N_EDGES) ? ei[N_EDGES + e] : e - N_EDGES;
    atomicAdd(&g_deg[d], 1);
}
__global__ __launch_bounds__(1024) void k_scan() {
    __shared__ int sp[1024];
    int t = threadIdx.x;
    const int CH = (N_NODES + 1023) / 1024;
    int base = t * CH, s = 0;
    for (int i = 0; i < CH; i++) { int idx = base + i; if (idx < N_NODES) s += g_deg[idx]; }
    sp[t] = s;
    __syncthreads();
    for (int o = 1; o < 1024; o <<= 1) {
        int v = (t >= o) ? sp[t - o] : 0;
        __syncthreads();
        sp[t] += v;
        __syncthreads();
    }
    int run = (t == 0) ? 0 : sp[t - 1];
    for (int i = 0; i < CH; i++) {
        int idx = base + i;
        if (idx < N_NODES) { g_off[idx] = run; run += g_deg[idx]; }
    }
    if (t == 1023) g_off[N_NODES] = sp[1023];
}
__global__ void k_scatter(const int* __restrict__ ei) {
    int e = blockIdx.x * blockDim.x + threadIdx.x;
    if (e >= TOT_E) return;
    int s, d;
    if (e < N_EDGES) { s = ei[e]; d = ei[N_EDGES + e]; } else { s = d = e - N_EDGES; }
    int pos = g_off[d] + atomicAdd(&g_cursor[d], 1);
    g_csr_src[pos] = s;
}

// ---------------- W1 bf16 hi/lo conversion (transpose to [n][k]) -----------
__global__ void k_cvt_w(const float* __restrict__ W1) {
    int i = blockIdx.x * blockDim.x + threadIdx.x;
    if (i >= F1 * IN_CH) return;
    int n = i >> 7, k = i & 127;
    float v = W1[(size_t)k * F1 + n];
    __nv_bfloat16 hi = __float2bfloat16_rn(v);
    g_w1hi[i] = hi;
    g_w1lo[i] = __float2bfloat16_rn(v - __bfloat162float(hi));
}

// ======== GEMM1 via mma.sync bf16 hi/lo: H1 = x @ W1, fused att dots =======
#define LDT 136                       // SMEM row stride in bf16 (272B)
#define TILE_BYTES (128 * LDT * 2)    // 34816
#define SH_ATTS 0
#define SH_ATTD 2048
#define SH_A_HI 4096
#define SH_A_LO (SH_A_HI + TILE_BYTES)
#define SH_B_HI (SH_A_LO + TILE_BYTES)
#define SH_B_LO (SH_B_HI + TILE_BYTES)
#define SH_TOTAL (SH_B_LO + TILE_BYTES)

__device__ __forceinline__ void load_tile128(char* dst, const __nv_bfloat16* src, int tid) {
#pragma unroll
    for (int it = 0; it < 16; it++) {
        int f = it * 256 + tid;
        int r = f >> 5;
        int c8 = (f & 31);
        *(uint2*)(dst + r * (LDT * 2) + c8 * 8) =
            *(const uint2*)(src + (size_t)r * 128 + c8 * 4);
    }
}
// load fp32 x tile, split into bf16 hi/lo SMEM tiles in one pass
__device__ __forceinline__ void load_A_split(char* hi, char* lo,
                                             const float* __restrict__ x,
                                             int m0, int tid) {
#pragma unroll
    for (int it = 0; it < 16; it++) {
        int f = it * 256 + tid;          // float4 id 0..4095
        int r = f >> 5;
        int c4 = (f & 31) * 4;
        int gm = m0 + r;
        float4 v = (gm < N_NODES) ? *(const float4*)(x + (size_t)gm * IN_CH + c4)
                                  : make_float4(0.f, 0.f, 0.f, 0.f);
        __nv_bfloat16 h0 = __float2bfloat16_rn(v.x), h1 = __float2bfloat16_rn(v.y);
        __nv_bfloat16 h2 = __float2bfloat16_rn(v.z), h3 = __float2bfloat16_rn(v.w);
        __nv_bfloat16 l0 = __float2bfloat16_rn(v.x - __bfloat162float(h0));
        __nv_bfloat16 l1 = __float2bfloat16_rn(v.y - __bfloat162float(h1));
        __nv_bfloat16 l2 = __float2bfloat16_rn(v.z - __bfloat162float(h2));
        __nv_bfloat16 l3 = __float2bfloat16_rn(v.w - __bfloat162float(h3));
        uint2 ph, pl;
        ph.x = (uint32_t)__bfloat16_as_ushort(h0) | ((uint32_t)__bfloat16_as_ushort(h1) << 16);
        ph.y = (uint32_t)__bfloat16_as_ushort(h2) | ((uint32_t)__bfloat16_as_ushort(h3) << 16);
        pl.x = (uint32_t)__bfloat16_as_ushort(l0) | ((uint32_t)__bfloat16_as_ushort(l1) << 16);
        pl.y = (uint32_t)__bfloat16_as_ushort(l2) | ((uint32_t)__bfloat16_as_ushort(l3) << 16);
        *(uint2*)(hi + r * (LDT * 2) + c4 * 2) = ph;
        *(uint2*)(lo + r * (LDT * 2) + c4 * 2) = pl;
    }
}

__global__ __launch_bounds__(256) void k_mma1(const float* __restrict__ x,
                                              const float* __restrict__ att_s,
                                              const float* __restrict__ att_d) {
    extern __shared__ char smem[];
    int tid = threadIdx.x;
    int wid = tid >> 5, lane = tid & 31;
    int wm = wid & 3;        // m group (32 rows)
    int wn = wid >> 2;       // n half (64 cols of the 128-chunk)
    int m0 = blockIdx.x * 128;

    for (int i = tid; i < 512; i += 256) {
        ((float*)(smem + SH_ATTS))[i] = att_s[i];
        ((float*)(smem + SH_ATTD))[i] = att_d[i];
    }
    load_A_split(smem + SH_A_HI, smem + SH_A_LO, x, m0, tid);

    uint32_t sb = smem_u32(smem);
    uint32_t abase[3] = { sb + SH_A_HI, sb + SH_A_HI, sb + SH_A_LO };
    uint32_t bbase[3] = { sb + SH_B_HI, sb + SH_B_LO, sb + SH_B_HI };

    uint32_t a_row_off[2], b_row_off[4];
#pragma unroll
    for (int mf = 0; mf < 2; mf++)
        a_row_off[mf] = (uint32_t)(wm * 32 + mf * 16 + (lane & 7) + ((lane >> 3) & 1) * 8) * (LDT * 2);
#pragma unroll
    for (int jj = 0; jj < 4; jj++)
        b_row_off[jj] = (uint32_t)(wn * 64 + jj * 16 + (lane & 7) + (lane >> 4) * 8) * (LDT * 2);
    uint32_t a_k_lane = ((uint32_t)(lane >> 4) * 8) * 2;
    uint32_t b_k_lane = ((uint32_t)((lane >> 3) & 1) * 8) * 2;

    const float* sas = (const float*)(smem + SH_ATTS);
    const float* sad = (const float*)(smem + SH_ATTD);

    for (int chunk = 0; chunk < 4; chunk++) {
        __syncthreads();
        load_tile128(smem + SH_B_HI, g_w1hi + (size_t)chunk * 128 * 128, tid);
        load_tile128(smem + SH_B_LO, g_w1lo + (size_t)chunk * 128 * 128, tid);
        __syncthreads();

        float acc[2][8][4];
#pragma unroll
        for (int mf = 0; mf < 2; mf++)
#pragma unroll
            for (int nf = 0; nf < 8; nf++)
#pragma unroll
                for (int q = 0; q < 4; q++) acc[mf][nf][q] = 0.f;

        for (int term = 0; term < 3; term++) {
            uint32_t ab = abase[term], bb = bbase[term];
            for (int kb = 0; kb < 8; kb++) {
                uint32_t akoff = (uint32_t)(kb * 16) * 2 + a_k_lane;
                uint32_t bkoff = (uint32_t)(kb * 16) * 2 + b_k_lane;
                uint32_t afr[2][4], bfr[4][4];
#pragma unroll
                for (int mf = 0; mf < 2; mf++) ldsm4(afr[mf], ab + a_row_off[mf] + akoff);
#pragma unroll
                for (int jj = 0; jj < 4; jj++) ldsm4(bfr[jj], bb + b_row_off[jj] + bkoff);
#pragma unroll
                for (int mf = 0; mf < 2; mf++)
#pragma unroll
                    for (int nf = 0; nf < 8; nf++)
                        mma16816(acc[mf][nf], afr[mf],
                                 bfr[nf >> 1][(nf & 1) * 2], bfr[nf >> 1][(nf & 1) * 2 + 1]);
            }
        }

        int head = chunk * 2 + wn;
        float ps[2][2] = {}, pd[2][2] = {};
#pragma unroll
        for (int nf = 0; nf < 8; nf++) {
            int cl = nf * 8 + (lane & 3) * 2;
            int col = head * 64 + cl;
            float2 wa = *(const float2*)(sas + col);
            float2 wd = *(const float2*)(sad + col);
#pragma unroll
            for (int mf = 0; mf < 2; mf++)
#pragma unroll
                for (int rh = 0; rh < 2; rh++) {
                    float d0 = acc[mf][nf][rh * 2], d1 = acc[mf][nf][rh * 2 + 1];
                    int row = m0 + wm * 32 + mf * 16 + rh * 8 + (lane >> 2);
                    if (row < N_NODES)
                        *(__half2*)(g_H1h + (size_t)row * F1 + col) = __floats2half2_rn(d0, d1);
                    ps[mf][rh] += d0 * wa.x + d1 * wa.y;
                    pd[mf][rh] += d0 * wd.x + d1 * wd.y;
                }
        }
#pragma unroll
        for (int mf = 0; mf < 2; mf++)
#pragma unroll
            for (int rh = 0; rh < 2; rh++) {
                float s = ps[mf][rh], d = pd[mf][rh];
                s += __shfl_xor_sync(0xffffffffu, s, 1);
                s += __shfl_xor_sync(0xffffffffu, s, 2);
                d += __shfl_xor_sync(0xffffffffu, d, 1);
                d += __shfl_xor_sync(0xffffffffu, d, 2);
                int row = m0 + wm * 32 + mf * 16 + rh * 8 + (lane >> 2);
                if ((lane & 3) == 0 && row < N_NODES) {
                    g_as1[row * 8 + head] = s;
                    g_ad1[row * 8 + head] = d;
                }
            }
    }
}

// ---- layer-1 CSR aggregation (fp16 gather), warp per dst ------------------
__global__ __launch_bounds__(256) void k_agg1(const float* __restrict__ b1) {
    int d = (blockIdx.x * blockDim.x + threadIdx.x) >> 5;
    int lane = threadIdx.x & 31;
    if (d >= N_NODES) return;
    int beg = g_off[d], end = g_off[d + 1];
    float ad = (lane < HEADS) ? g_ad1[d * 8 + lane] : 0.f;
    float den = 0.f;
    float acc[2][8] = {};
    int hq = lane >> 3;                         // 0..3
    for (int k = beg; k < end; k++) {
        int s = g_csr_src[k];
        float ee = 0.f;
        if (lane < HEADS) {
            float e = lrelu(g_as1[s * 8 + lane] + ad);
            ee = __expf(e);
            den += ee;
        }
        const uint4* hp = (const uint4*)(g_H1h + (size_t)s * F1);
#pragma unroll
        for (int i = 0; i < 2; i++) {
            float w = __shfl_sync(0xffffffffu, ee, i * 4 + hq);
            uint4 v = hp[i * 32 + lane];        // 8 halves
            const __half2* p2 = (const __half2*)&v;
#pragma unroll
            for (int j2 = 0; j2 < 4; j2++) {
                float2 f = __half22float2(p2[j2]);
                acc[i][j2 * 2]     += w * f.x;
                acc[i][j2 * 2 + 1] += w * f.y;
            }
        }
    }
    // per-head normalize
    float t[8];
#pragma unroll
    for (int i = 0; i < 2; i++) {
        float dh = __shfl_sync(0xffffffffu, den, i * 4 + hq);
        float inv = 1.f / dh;
#pragma unroll
        for (int j = 0; j < 8; j++) acc[i][j] *= inv;
    }
#pragma unroll
    for (int j = 0; j < 8; j++) t[j] = acc[0][j] + acc[1][j];
    // sum over the 4 head groups sharing this channel octet
#pragma unroll
    for (int j = 0; j < 8; j++) {
        t[j] += __shfl_xor_sync(0xffffffffu, t[j], 8);
        t[j] += __shfl_xor_sync(0xffffffffu, t[j], 16);
    }
    if (lane < 8) {
        int c0 = lane * 8;
        float4 b0 = *(const float4*)(b1 + c0);
        float4 b4 = *(const float4*)(b1 + c0 + 4);
        float o[8];
        o[0] = t[0] * 0.125f + b0.x; o[1] = t[1] * 0.125f + b0.y;
        o[2] = t[2] * 0.125f + b0.z; o[3] = t[3] * 0.125f + b0.w;
        o[4] = t[4] * 0.125f + b4.x; o[5] = t[5] * 0.125f + b4.y;
        o[6] = t[6] * 0.125f + b4.z; o[7] = t[7] * 0.125f + b4.w;
#pragma unroll
        for (int j = 0; j < 8; j++) o[j] = o[j] > 0.f ? o[j] : expm1f(o[j]);
        *(float4*)(g_X2 + (size_t)d * OUT_CH + c0)     = make_float4(o[0], o[1], o[2], o[3]);
        *(float4*)(g_X2 + (size_t)d * OUT_CH + c0 + 4) = make_float4(o[4], o[5], o[6], o[7]);
    }
}

// ---------------- GEMM2: H2[N,64] = X2[N,64] @ W2[64,64] (fp16 out) --------
__global__ __launch_bounds__(256) void k_gemm2(const float* __restrict__ W2) {
    __shared__ float ws[64 * 64];
    __shared__ float xs[16][64];
    int tid = threadIdx.x;
    for (int i = tid; i < 64 * 64; i += 256) ws[i] = W2[i];
    int r0 = blockIdx.x * 16;
    for (int i = tid; i < 16 * 64; i += 256) {
        int r = i >> 6, c = i & 63;
        xs[r][c] = g_X2[(size_t)(r0 + r) * 64 + c];
    }
    __syncthreads();
    int c = tid & 63;
    int rg = tid >> 6;
    float acc[4] = {0.f, 0.f, 0.f, 0.f};
    for (int k = 0; k < 64; k++) {
        float w = ws[k * 64 + c];
#pragma unroll
        for (int j = 0; j < 4; j++) acc[j] += xs[rg * 4 + j][k] * w;
    }
#pragma unroll
    for (int j = 0; j < 4; j++)
        g_H2h[(size_t)(r0 + rg * 4 + j) * 64 + c] = __float2half_rn(acc[j]);
}

// ---------------- attention dots layer 2 (fp16 H2) -------------------------
__global__ __launch_bounds__(256) void k_att2(const float* __restrict__ att_s,
                                              const float* __restrict__ att_d) {
    int warp = (blockIdx.x * blockDim.x + threadIdx.x) >> 5;
    int lane = threadIdx.x & 31;
    if (warp >= N_NODES) return;
    const __half2* hrow = (const __half2*)(g_H2h + (size_t)warp * 64);
    float2 f = __half22float2(hrow[lane]);
    float s = f.x * att_s[lane * 2] + f.y * att_s[lane * 2 + 1];
    float d = f.x * att_d[lane * 2] + f.y * att_d[lane * 2 + 1];
#pragma unroll
    for (int o = 16; o; o >>= 1) {
        s += __shfl_xor_sync(0xffffffffu, s, o);
        d += __shfl_xor_sync(0xffffffffu, d, o);
    }
    if (lane == 0) { g_as2[warp] = s; g_ad2[warp] = d; }
}

// ---- layer-2 CSR aggregation (fp16 gather), warp per dst ------------------
__global__ __launch_bounds__(256) void k_agg2(const float* __restrict__ b2,
                                              float* __restrict__ out) {
    int d = (blockIdx.x * blockDim.x + threadIdx.x) >> 5;
    int lane = threadIdx.x & 31;
    if (d >= N_NODES) return;
    int beg = g_off[d], end = g_off[d + 1];
    float ad = g_ad2[d];
    float den = 0.f;
    float2 acc = make_float2(0.f, 0.f);
    for (int k = beg; k < end; k++) {
        int s = g_csr_src[k];
        float ee = __expf(lrelu(g_as2[s] + ad));
        den += ee;
        float2 f = __half22float2(((const __half2*)(g_H2h + (size_t)s * 64))[lane]);
        acc.x += ee * f.x; acc.y += ee * f.y;
    }
    float inv = 1.f / den;
    float2 bb = *(const float2*)(b2 + lane * 2);
    *(float2*)(out + (size_t)d * 64 + lane * 2) =
        make_float2(acc.x * inv + bb.x, acc.y * inv + bb.y);
}

// ---------------------------------------------------------------------------
extern "C" void kernel_launch(void* const* d_in, const int* in_sizes, int n_in,
                              void* d_out, int out_size) {
    const float* x   = (const float*)d_in[0];
    const int*   ei  = (const int*)  d_in[1];
    const float* W1  = (const float*)d_in[2];
    const float* as1 = (const float*)d_in[3];
    const float* ad1 = (const float*)d_in[4];
    const float* b1  = (const float*)d_in[5];
    const float* W2  = (const float*)d_in[6];
    const float* as2 = (const float*)d_in[7];
    const float* ad2 = (const float*)d_in[8];
    const float* b2  = (const float*)d_in[9];
    float* out = (float*)d_out;

    static int smem_set = 0;
    if (!smem_set) {
        cudaFuncSetAttribute(k_mma1, cudaFuncAttributeMaxDynamicSharedMemorySize, SH_TOTAL);
        smem_set = 1;
    }

    k_init<<<(N_NODES + 255) / 256, 256>>>();
    k_hist<<<(TOT_E + 255) / 256, 256>>>(ei);
    k_scan<<<1, 1024>>>();
    k_scatter<<<(TOT_E + 255) / 256, 256>>>(ei);
    k_cvt_w<<<(F1 * IN_CH + 255) / 256, 256>>>(W1);

    // layer 1
    k_mma1<<<M_TILES, 256, SH_TOTAL>>>(x, as1, ad1);
    k_agg1<<<(N_NODES * 32 + 255) / 256, 256>>>(b1);

    // layer 2
    k_gemm2<<<N_NODES / 16, 256>>>(W2);
    k_att2<<<(N_NODES + 7) / 8, 256>>>(as2, ad2);
    k_agg2<<<(N_NODES * 32 + 255) / 256, 256>>>(b2, out);
}

// round 7
// speedup vs baseline: 2.9285x; 1.1631x over previous
#include <cuda_runtime.h>
#include <cuda_bf16.h>
#include <cuda_fp16.h>
#include <math.h>
#include <stdint.h>

#define N_NODES 50000
#define N_EDGES 400000
#define TOT_E   (N_EDGES + N_NODES)
#define IN_CH   128
#define OUT_CH  64
#define HEADS   8
#define F1      (HEADS * OUT_CH)      // 512
#define M_TILES 391

// ---------------- device scratch -------------------------------------------
__device__ __align__(16) __half g_H1h[N_NODES * F1];     // layer-1 features, fp16
__device__ __align__(16) float g_as1[N_NODES * HEADS];
__device__ __align__(16) float g_ad1[N_NODES * HEADS];
__device__ __align__(16) float g_X2[N_NODES * OUT_CH];
__device__ __align__(16) __half g_H2h[N_NODES * OUT_CH];
__device__ __align__(16) float g_as2[N_NODES];
__device__ __align__(16) float g_ad2[N_NODES];
__device__ __align__(16) __nv_bfloat16 g_w1hi[F1 * IN_CH];   // [n][k] transposed
__device__ __align__(16) __nv_bfloat16 g_w1lo[F1 * IN_CH];
// CSR by destination
__device__ int g_deg[N_NODES];
__device__ int g_cursor[N_NODES];
__device__ int g_off[N_NODES + 1];
__device__ int g_csr_src[TOT_E];

__device__ __forceinline__ float lrelu(float v) { return v > 0.f ? v : 0.2f * v; }

__device__ __forceinline__ uint32_t smem_u32(const void* p) {
    uint32_t a;
    asm("{ .reg .u64 t; cvta.to.shared.u64 t, %1; cvt.u32.u64 %0, t; }"
        : "=r"(a) : "l"(p));
    return a;
}
__device__ __forceinline__ void ldsm4(uint32_t* r, uint32_t addr) {
    asm volatile("ldmatrix.sync.aligned.m8n8.x4.shared.b16 {%0,%1,%2,%3}, [%4];"
                 : "=r"(r[0]), "=r"(r[1]), "=r"(r[2]), "=r"(r[3]) : "r"(addr));
}
__device__ __forceinline__ void mma16816(float* d, const uint32_t* a,
                                         const uint32_t b0, const uint32_t b1) {
    asm volatile("mma.sync.aligned.m16n8k16.row.col.f32.bf16.bf16.f32 "
                 "{%0,%1,%2,%3}, {%4,%5,%6,%7}, {%8,%9}, {%0,%1,%2,%3};"
                 : "+f"(d[0]), "+f"(d[1]), "+f"(d[2]), "+f"(d[3])
                 : "r"(a[0]), "r"(a[1]), "r"(a[2]), "r"(a[3]), "r"(b0), "r"(b1));
}

// ---------------- init + CSR build -----------------------------------------
__global__ void k_init() {
    int i = blockIdx.x * blockDim.x + threadIdx.x;
    if (i < N_NODES) { g_deg[i] = 0; g_cursor[i] = 0; }
}
__global__ void k_hist(const int* __restrict__ ei) {
    int e = blockIdx.x * blockDim.x + threadIdx.x;
    if (e >= TOT_E) return;
    int d = (e < N_EDGES) ? ei[N_EDGES + e] : e - N_EDGES;
    atomicAdd(&g_deg[d], 1);
}
__global__ __launch_bounds__(1024) void k_scan() {
    __shared__ int sp[1024];
    int t = threadIdx.x;
    const int CH = (N_NODES + 1023) / 1024;
    int base = t * CH, s = 0;
    for (int i = 0; i < CH; i++) { int idx = base + i; if (idx < N_NODES) s += g_deg[idx]; }
    sp[t] = s;
    __syncthreads();
    for (int o = 1; o < 1024; o <<= 1) {
        int v = (t >= o) ? sp[t - o] : 0;
        __syncthreads();
        sp[t] += v;
        __syncthreads();
    }
    int run = (t == 0) ? 0 : sp[t - 1];
    for (int i = 0; i < CH; i++) {
        int idx = base + i;
        if (idx < N_NODES) { g_off[idx] = run; run += g_deg[idx]; }
    }
    if (t == 1023) g_off[N_NODES] = sp[1023];
}
__global__ void k_scatter(const int* __restrict__ ei) {
    int e = blockIdx.x * blockDim.x + threadIdx.x;
    if (e >= TOT_E) return;
    int s, d;
    if (e < N_EDGES) { s = ei[e]; d = ei[N_EDGES + e]; } else { s = d = e - N_EDGES; }
    int pos = g_off[d] + atomicAdd(&g_cursor[d], 1);
    g_csr_src[pos] = s;
}

// ---------------- W1 bf16 hi/lo conversion (transpose to [n][k]) -----------
__global__ void k_cvt_w(const float* __restrict__ W1) {
    int i = blockIdx.x * blockDim.x + threadIdx.x;
    if (i >= F1 * IN_CH) return;
    int n = i >> 7, k = i & 127;
    float v = W1[(size_t)k * F1 + n];
    __nv_bfloat16 hi = __float2bfloat16_rn(v);
    g_w1hi[i] = hi;
    g_w1lo[i] = __float2bfloat16_rn(v - __bfloat162float(hi));
}

// ======== GEMM1 via mma.sync bf16 hi/lo: H1 = x @ W1, fused att dots =======
#define LDT 136                       // SMEM row stride in bf16 (272B)
#define TILE_BYTES (128 * LDT * 2)    // 34816
#define SH_ATTS 0
#define SH_ATTD 2048
#define SH_A_HI 4096
#define SH_A_LO (SH_A_HI + TILE_BYTES)
#define SH_B0_HI (SH_A_LO + TILE_BYTES)
#define SH_B1_HI (SH_B0_HI + 2 * TILE_BYTES)
#define SH_TOTAL (SH_B1_HI + 2 * TILE_BYTES)   // 212992 B

// async copy of one 128x128 bf16 tile into SMEM (LDT stride)
__device__ __forceinline__ void copy_tile_async(uint32_t dst_sb,
                                                const __nv_bfloat16* __restrict__ src,
                                                int tid) {
#pragma unroll
    for (int it = 0; it < 8; it++) {
        int f = it * 256 + tid;          // 16B chunk id, 0..2047
        int r = f >> 4;
        int c16 = f & 15;
        uint32_t d = dst_sb + (uint32_t)r * (LDT * 2) + (uint32_t)c16 * 16;
        const void* s = src + (size_t)r * 128 + c16 * 8;
        asm volatile("cp.async.cg.shared.global [%0], [%1], 16;" :: "r"(d), "l"(s));
    }
}
// load fp32 x tile, split into bf16 hi/lo SMEM tiles in one pass
__device__ __forceinline__ void load_A_split(char* hi, char* lo,
                                             const float* __restrict__ x,
                                             int m0, int tid) {
#pragma unroll
    for (int it = 0; it < 16; it++) {
        int f = it * 256 + tid;          // float4 id 0..4095
        int r = f >> 5;
        int c4 = (f & 31) * 4;
        int gm = m0 + r;
        float4 v = (gm < N_NODES) ? *(const float4*)(x + (size_t)gm * IN_CH + c4)
                                  : make_float4(0.f, 0.f, 0.f, 0.f);
        __nv_bfloat16 h0 = __float2bfloat16_rn(v.x), h1 = __float2bfloat16_rn(v.y);
        __nv_bfloat16 h2 = __float2bfloat16_rn(v.z), h3 = __float2bfloat16_rn(v.w);
        __nv_bfloat16 l0 = __float2bfloat16_rn(v.x - __bfloat162float(h0));
        __nv_bfloat16 l1 = __float2bfloat16_rn(v.y - __bfloat162float(h1));
        __nv_bfloat16 l2 = __float2bfloat16_rn(v.z - __bfloat162float(h2));
        __nv_bfloat16 l3 = __float2bfloat16_rn(v.w - __bfloat162float(h3));
        uint2 ph, pl;
        ph.x = (uint32_t)__bfloat16_as_ushort(h0) | ((uint32_t)__bfloat16_as_ushort(h1) << 16);
        ph.y = (uint32_t)__bfloat16_as_ushort(h2) | ((uint32_t)__bfloat16_as_ushort(h3) << 16);
        pl.x = (uint32_t)__bfloat16_as_ushort(l0) | ((uint32_t)__bfloat16_as_ushort(l1) << 16);
        pl.y = (uint32_t)__bfloat16_as_ushort(l2) | ((uint32_t)__bfloat16_as_ushort(l3) << 16);
        *(uint2*)(hi + r * (LDT * 2) + c4 * 2) = ph;
        *(uint2*)(lo + r * (LDT * 2) + c4 * 2) = pl;
    }
}

__global__ __launch_bounds__(256) void k_mma1(const float* __restrict__ x,
                                              const float* __restrict__ att_s,
                                              const float* __restrict__ att_d) {
    extern __shared__ char smem[];
    int tid = threadIdx.x;
    int wid = tid >> 5, lane = tid & 31;
    int wm = wid & 3;        // m group (32 rows)
    int wn = wid >> 2;       // n half (64 cols of the 128-chunk)
    int m0 = blockIdx.x * 128;
    uint32_t sb = smem_u32(smem);

    // prefetch B chunk 0 (hi+lo) while we stage A/att
    copy_tile_async(sb + SH_B0_HI, g_w1hi, tid);
    copy_tile_async(sb + SH_B0_HI + TILE_BYTES, g_w1lo, tid);
    asm volatile("cp.async.commit_group;" ::: "memory");

    for (int i = tid; i < 512; i += 256) {
        ((float*)(smem + SH_ATTS))[i] = att_s[i];
        ((float*)(smem + SH_ATTD))[i] = att_d[i];
    }
    load_A_split(smem + SH_A_HI, smem + SH_A_LO, x, m0, tid);

    uint32_t abase[3] = { sb + SH_A_HI, sb + SH_A_HI, sb + SH_A_LO };

    uint32_t a_row_off[2], b_row_off[4];
#pragma unroll
    for (int mf = 0; mf < 2; mf++)
        a_row_off[mf] = (uint32_t)(wm * 32 + mf * 16 + (lane & 7) + ((lane >> 3) & 1) * 8) * (LDT * 2);
#pragma unroll
    for (int jj = 0; jj < 4; jj++)
        b_row_off[jj] = (uint32_t)(wn * 64 + jj * 16 + (lane & 7) + (lane >> 4) * 8) * (LDT * 2);
    uint32_t a_k_lane = ((uint32_t)(lane >> 4) * 8) * 2;
    uint32_t b_k_lane = ((uint32_t)((lane >> 3) & 1) * 8) * 2;

    const float* sas = (const float*)(smem + SH_ATTS);
    const float* sad = (const float*)(smem + SH_ATTD);

    for (int chunk = 0; chunk < 4; chunk++) {
        if (chunk < 3) {   // prefetch next B into alternate buffer
            uint32_t nb = sb + (((chunk + 1) & 1) ? SH_B1_HI : SH_B0_HI);
            copy_tile_async(nb, g_w1hi + (size_t)(chunk + 1) * 128 * 128, tid);
            copy_tile_async(nb + TILE_BYTES, g_w1lo + (size_t)(chunk + 1) * 128 * 128, tid);
            asm volatile("cp.async.commit_group;" ::: "memory");
            asm volatile("cp.async.wait_group 1;" ::: "memory");
        } else {
            asm volatile("cp.async.wait_group 0;" ::: "memory");
        }
        __syncthreads();

        uint32_t bufb = sb + ((chunk & 1) ? SH_B1_HI : SH_B0_HI);
        uint32_t bbase[3] = { bufb, bufb + TILE_BYTES, bufb };

        float acc[2][8][4];
#pragma unroll
        for (int mf = 0; mf < 2; mf++)
#pragma unroll
            for (int nf = 0; nf < 8; nf++)
#pragma unroll
                for (int q = 0; q < 4; q++) acc[mf][nf][q] = 0.f;

        for (int term = 0; term < 3; term++) {
            uint32_t ab = abase[term], bb = bbase[term];
            for (int kb = 0; kb < 8; kb++) {
                uint32_t akoff = (uint32_t)(kb * 16) * 2 + a_k_lane;
                uint32_t bkoff = (uint32_t)(kb * 16) * 2 + b_k_lane;
                uint32_t afr[2][4], bfr[4][4];
#pragma unroll
                for (int mf = 0; mf < 2; mf++) ldsm4(afr[mf], ab + a_row_off[mf] + akoff);
#pragma unroll
                for (int jj = 0; jj < 4; jj++) ldsm4(bfr[jj], bb + b_row_off[jj] + bkoff);
#pragma unroll
                for (int mf = 0; mf < 2; mf++)
#pragma unroll
                    for (int nf = 0; nf < 8; nf++)
                        mma16816(acc[mf][nf], afr[mf],
                                 bfr[nf >> 1][(nf & 1) * 2], bfr[nf >> 1][(nf & 1) * 2 + 1]);
            }
        }
        __syncthreads();   // done reading this B buffer (rewritten at chunk+2)

        int head = chunk * 2 + wn;
        float ps[2][2] = {}, pd[2][2] = {};
#pragma unroll
        for (int nf = 0; nf < 8; nf++) {
            int cl = nf * 8 + (lane & 3) * 2;
            int col = head * 64 + cl;
            float2 wa = *(const float2*)(sas + col);
            float2 wd = *(const float2*)(sad + col);
#pragma unroll
            for (int mf = 0; mf < 2; mf++)
#pragma unroll
                for (int rh = 0; rh < 2; rh++) {
                    float d0 = acc[mf][nf][rh * 2], d1 = acc[mf][nf][rh * 2 + 1];
                    int row = m0 + wm * 32 + mf * 16 + rh * 8 + (lane >> 2);
                    if (row < N_NODES)
                        *(__half2*)(g_H1h + (size_t)row * F1 + col) = __floats2half2_rn(d0, d1);
                    ps[mf][rh] += d0 * wa.x + d1 * wa.y;
                    pd[mf][rh] += d0 * wd.x + d1 * wd.y;
                }
        }
#pragma unroll
        for (int mf = 0; mf < 2; mf++)
#pragma unroll
            for (int rh = 0; rh < 2; rh++) {
                float s = ps[mf][rh], d = pd[mf][rh];
                s += __shfl_xor_sync(0xffffffffu, s, 1);
                s += __shfl_xor_sync(0xffffffffu, s, 2);
                d += __shfl_xor_sync(0xffffffffu, d, 1);
                d += __shfl_xor_sync(0xffffffffu, d, 2);
                int row = m0 + wm * 32 + mf * 16 + rh * 8 + (lane >> 2);
                if ((lane & 3) == 0 && row < N_NODES) {
                    g_as1[row * 8 + head] = s;
                    g_ad1[row * 8 + head] = d;
                }
            }
    }
}

// ---- layer-1 CSR aggregation (fp16 gather), warp per dst ------------------
__global__ __launch_bounds__(256) void k_agg1(const float* __restrict__ b1) {
    int d = (blockIdx.x * blockDim.x + threadIdx.x) >> 5;
    int lane = threadIdx.x & 31;
    if (d >= N_NODES) return;
    int beg = g_off[d], end = g_off[d + 1];
    float ad = (lane < HEADS) ? g_ad1[d * 8 + lane] : 0.f;
    float den = 0.f;
    float acc[2][8] = {};
    int hq = lane >> 3;                         // 0..3
    for (int k = beg; k < end; k++) {
        int s = g_csr_src[k];
        float ee = 0.f;
        if (lane < HEADS) {
            float e = lrelu(g_as1[s * 8 + lane] + ad);
            ee = __expf(e);
            den += ee;
        }
        const uint4* hp = (const uint4*)(g_H1h + (size_t)s * F1);
#pragma unroll
        for (int i = 0; i < 2; i++) {
            float w = __shfl_sync(0xffffffffu, ee, i * 4 + hq);
            uint4 v = hp[i * 32 + lane];        // 8 halves
            const __half2* p2 = (const __half2*)&v;
#pragma unroll
            for (int j2 = 0; j2 < 4; j2++) {
                float2 f = __half22float2(p2[j2]);
                acc[i][j2 * 2]     += w * f.x;
                acc[i][j2 * 2 + 1] += w * f.y;
            }
        }
    }
    float t[8];
#pragma unroll
    for (int i = 0; i < 2; i++) {
        float dh = __shfl_sync(0xffffffffu, den, i * 4 + hq);
        float inv = 1.f / dh;
#pragma unroll
        for (int j = 0; j < 8; j++) acc[i][j] *= inv;
    }
#pragma unroll
    for (int j = 0; j < 8; j++) t[j] = acc[0][j] + acc[1][j];
#pragma unroll
    for (int j = 0; j < 8; j++) {
        t[j] += __shfl_xor_sync(0xffffffffu, t[j], 8);
        t[j] += __shfl_xor_sync(0xffffffffu, t[j], 16);
    }
    if (lane < 8) {
        int c0 = lane * 8;
        float4 b0 = *(const float4*)(b1 + c0);
        float4 b4 = *(const float4*)(b1 + c0 + 4);
        float o[8];
        o[0] = t[0] * 0.125f + b0.x; o[1] = t[1] * 0.125f + b0.y;
        o[2] = t[2] * 0.125f + b0.z; o[3] = t[3] * 0.125f + b0.w;
        o[4] = t[4] * 0.125f + b4.x; o[5] = t[5] * 0.125f + b4.y;
        o[6] = t[6] * 0.125f + b4.z; o[7] = t[7] * 0.125f + b4.w;
#pragma unroll
        for (int j = 0; j < 8; j++) o[j] = o[j] > 0.f ? o[j] : expm1f(o[j]);
        *(float4*)(g_X2 + (size_t)d * OUT_CH + c0)     = make_float4(o[0], o[1], o[2], o[3]);
        *(float4*)(g_X2 + (size_t)d * OUT_CH + c0 + 4) = make_float4(o[4], o[5], o[6], o[7]);
    }
}

// -------- GEMM2 + fused attention dots: H2 = X2 @ W2, as2/ad2 --------------
__global__ __launch_bounds__(256) void k_gemm2(const float* __restrict__ W2,
                                               const float* __restrict__ as2v,
                                               const float* __restrict__ ad2v) {
    __shared__ float ws[64 * 64];
    __shared__ float xs[16][64];
    __shared__ float sred[8][8];
    int tid = threadIdx.x;
    for (int i = tid; i < 64 * 64; i += 256) ws[i] = W2[i];
    int r0 = blockIdx.x * 16;
    for (int i = tid; i < 16 * 64; i += 256) {
        int r = i >> 6, c = i & 63;
        xs[r][c] = g_X2[(size_t)(r0 + r) * 64 + c];
    }
    __syncthreads();
    int c = tid & 63;
    int rg = tid >> 6;
    int warp = tid >> 5, lane = tid & 31;
    float acc[4] = {0.f, 0.f, 0.f, 0.f};
    for (int k = 0; k < 64; k++) {
        float w = ws[k * 64 + c];
#pragma unroll
        for (int j = 0; j < 4; j++) acc[j] += xs[rg * 4 + j][k] * w;
    }
    float sa = __ldg(as2v + c), da = __ldg(ad2v + c);
    float sp[4], dp[4];
#pragma unroll
    for (int j = 0; j < 4; j++) {
        g_H2h[(size_t)(r0 + rg * 4 + j) * 64 + c] = __float2half_rn(acc[j]);
        sp[j] = acc[j] * sa;
        dp[j] = acc[j] * da;
    }
#pragma unroll
    for (int o = 16; o; o >>= 1)
#pragma unroll
        for (int j = 0; j < 4; j++) {
            sp[j] += __shfl_xor_sync(0xffffffffu, sp[j], o);
            dp[j] += __shfl_xor_sync(0xffffffffu, dp[j], o);
        }
    if (lane == 0) {
#pragma unroll
        for (int j = 0; j < 4; j++) { sred[warp][j] = sp[j]; sred[warp][4 + j] = dp[j]; }
    }
    __syncthreads();
    if (tid < 32) {
        int rg2 = tid >> 3, j = (tid >> 1) & 3, sv = tid & 1;
        float v = sred[rg2 * 2][sv * 4 + j] + sred[rg2 * 2 + 1][sv * 4 + j];
        int row = r0 + rg2 * 4 + j;
        if (sv == 0) g_as2[row] = v; else g_ad2[row] = v;
    }
}

// ---- layer-2 CSR aggregation (fp16 gather), warp per dst ------------------
__global__ __launch_bounds__(256) void k_agg2(const float* __restrict__ b2,
                                              float* __restrict__ out) {
    int d = (blockIdx.x * blockDim.x + threadIdx.x) >> 5;
    int lane = threadIdx.x & 31;
    if (d >= N_NODES) return;
    int beg = g_off[d], end = g_off[d + 1];
    float ad = g_ad2[d];
    float den = 0.f;
    float2 acc = make_float2(0.f, 0.f);
    for (int k = beg; k < end; k++) {
        int s = g_csr_src[k];
        float ee = __expf(lrelu(g_as2[s] + ad));
        den += ee;
        float2 f = __half22float2(((const __half2*)(g_H2h + (size_t)s * 64))[lane]);
        acc.x += ee * f.x; acc.y += ee * f.y;
    }
    float inv = 1.f / den;
    float2 bb = *(const float2*)(b2 + lane * 2);
    *(float2*)(out + (size_t)d * 64 + lane * 2) =
        make_float2(acc.x * inv + bb.x, acc.y * inv + bb.y);
}

// ---------------------------------------------------------------------------
extern "C" void kernel_launch(void* const* d_in, const int* in_sizes, int n_in,
                              void* d_out, int out_size) {
    const float* x   = (const float*)d_in[0];
    const int*   ei  = (const int*)  d_in[1];
    const float* W1  = (const float*)d_in[2];
    const float* as1 = (const float*)d_in[3];
    const float* ad1 = (const float*)d_in[4];
    const float* b1  = (const float*)d_in[5];
    const float* W2  = (const float*)d_in[6];
    const float* as2 = (const float*)d_in[7];
    const float* ad2 = (const float*)d_in[8];
    const float* b2  = (const float*)d_in[9];
    float* out = (float*)d_out;

    static cudaStream_t s1;
    static cudaEvent_t ev0, ev1;
    static int inited = 0;
    if (!inited) {   // first call is the uncaptured correctness run
        cudaFuncSetAttribute(k_mma1, cudaFuncAttributeMaxDynamicSharedMemorySize, SH_TOTAL);
        cudaStreamCreateWithFlags(&s1, cudaStreamNonBlocking);
        cudaEventCreateWithFlags(&ev0, cudaEventDisableTiming);
        cudaEventCreateWithFlags(&ev1, cudaEventDisableTiming);
        inited = 1;
    }

    // fork: CSR build on side stream, concurrent with cvt_w + mma1
    cudaEventRecord(ev0, 0);
    cudaStreamWaitEvent(s1, ev0, 0);
    k_init<<<(N_NODES + 255) / 256, 256, 0, s1>>>();
    k_hist<<<(TOT_E + 255) / 256, 256, 0, s1>>>(ei);
    k_scan<<<1, 1024, 0, s1>>>();
    k_scatter<<<(TOT_E + 255) / 256, 256, 0, s1>>>(ei);
    cudaEventRecord(ev1, s1);

    k_cvt_w<<<(F1 * IN_CH + 255) / 256, 256>>>(W1);
    k_mma1<<<M_TILES, 256, SH_TOTAL>>>(x, as1, ad1);

    // join: aggregation needs both CSR and H1
    cudaStreamWaitEvent(0, ev1, 0);
    k_agg1<<<(N_NODES * 32 + 255) / 256, 256>>>(b1);

    // layer 2
    k_gemm2<<<N_NODES / 16, 256>>>(W2, as2, ad2);
    k_agg2<<<(N_NODES * 32 + 255) / 256, 256>>>(b2, out);
}